// round 3
// baseline (speedup 1.0000x reference)
#include <cuda_runtime.h>

#define OUT_S 56
#define N_OUT 3136
#define NC_PER_GROUP 8192
#define HP_STRIDE 68          // smem row stride in floats (=4 mod 32)

// Separable AdaptiveAvgPool2d(56) from S in {24,32,48}: S/56 = NUM/7, NUM=S/8.
// Horizontal: each input-row half (S/2 cols) maps to exactly 28 output cols.
// Vertical: each 7-output strip consumes exactly NUM self-contained input rows.

template<int S>
__device__ __forceinline__ void run_group(const float* __restrict__ src,
                                          float mean, float sd,
                                          float* __restrict__ hp,    // [S][HP_STRIDE]
                                          float* __restrict__ outp,
                                          int tid)
{
    constexpr int NUM = S / 8;      // 3, 4, 6
    constexpr int CPH = S / 2;      // cols per half: 12, 16, 24 (all %4==0)

    // ---------- Phase A: global -> registers -> h-pool -> smem ----------
    if (tid < 2 * S) {
        const int h = (tid >= S) ? 1 : 0;
        const int r = tid - (h ? S : 0);
        const float* __restrict__ row = src + r * S + h * CPH;

        float v[CPH];
        #pragma unroll
        for (int k = 0; k < CPH / 4; k++) {
            float4 t = ((const float4*)row)[k];
            v[4*k+0] = t.x; v[4*k+1] = t.y; v[4*k+2] = t.z; v[4*k+3] = t.w;
        }
        #pragma unroll
        for (int k = 0; k < CPH; k++)
            v[k] = fmaxf(fmaf(v[k], sd, mean), 0.0f);

        float o[28];
        #pragma unroll
        for (int jr = 0; jr < 28; jr++) {
            constexpr_helper:;
            const int c0 = (jr * NUM) / 7;
            const int w  = ((jr + 1) * NUM + 6) / 7 - c0;
            o[jr] = (w == 2) ? (v[c0] + v[c0 + 1]) * 0.5f : v[c0];
        }

        float* dst = hp + r * HP_STRIDE + h * 28;
        #pragma unroll
        for (int k = 0; k < 7; k++)
            ((float4*)dst)[k] = make_float4(o[4*k], o[4*k+1], o[4*k+2], o[4*k+3]);
    }
    __syncthreads();

    // ---------- Phase B: smem rows -> registers -> v-pool -> global ----------
    // 112 threads = 8 strips (7 output rows each) x 14 float4 columns.
    if (tid < 112) {
        const int st = tid / 14;
        const int jc = tid - st * 14;

        const float* base = hp + st * (NUM * HP_STRIDE) + jc * 4;
        float4 rows[NUM];
        #pragma unroll
        for (int k = 0; k < NUM; k++)
            rows[k] = *(const float4*)(base + k * HP_STRIDE);

        float4* __restrict__ o4 = (float4*)outp + st * (7 * 14) + jc;
        #pragma unroll
        for (int i = 0; i < 7; i++) {
            const int r0 = (i * NUM) / 7;
            const int w  = ((i + 1) * NUM + 6) / 7 - r0;
            float4 res;
            if (w == 2) {
                res.x = (rows[r0].x + rows[r0+1].x) * 0.5f;
                res.y = (rows[r0].y + rows[r0+1].y) * 0.5f;
                res.z = (rows[r0].z + rows[r0+1].z) * 0.5f;
                res.w = (rows[r0].w + rows[r0+1].w) * 0.5f;
            } else {
                res = rows[r0];
            }
            o4[i * 14] = res;
        }
    }
}

__global__ __launch_bounds__(128)
void denorm_relu_pool_v3(const float* __restrict__ p24,
                         const float* __restrict__ p32,
                         const float* __restrict__ p48,
                         const float* __restrict__ smean,
                         const float* __restrict__ sstd,
                         float* __restrict__ out)
{
    __shared__ float hp[48 * HP_STRIDE];   // 13056 B

    const int gnc = blockIdx.x;                 // n*256 + c, global
    const int grp = gnc >> 13;
    const int local = gnc & (NC_PER_GROUP - 1);
    const int tid = threadIdx.x;

    const float mean = __ldg(smean + gnc);
    const float sd   = __ldg(sstd + gnc);
    float* outp = out + (size_t)gnc * N_OUT;

    if (grp == 0) {
        run_group<24>(p24 + (size_t)local * (24 * 24), mean, sd, hp, outp, tid);
    } else if (grp == 1) {
        run_group<32>(p32 + (size_t)local * (32 * 32), mean, sd, hp, outp, tid);
    } else {
        run_group<48>(p48 + (size_t)local * (48 * 48), mean, sd, hp, outp, tid);
    }
}

extern "C" void kernel_launch(void* const* d_in, const int* in_sizes, int n_in,
                              void* d_out, int out_size)
{
    const float* p24   = (const float*)d_in[0];
    const float* p32   = (const float*)d_in[1];
    const float* p48   = (const float*)d_in[2];
    const float* smean = (const float*)d_in[3];
    const float* sstd  = (const float*)d_in[4];
    float* out = (float*)d_out;

    denorm_relu_pool_v3<<<3 * NC_PER_GROUP, 128>>>(p24, p32, p48,
                                                   smean, sstd, out);
}